// round 2
// baseline (speedup 1.0000x reference)
#include <cuda_runtime.h>
#include <cuda_bf16.h>

// TensorDLT closed-form solve for fixed source corners
// (0,0),(127,0),(127,127),(0,127). 8 fp32 in -> 9 fp32 out per element.
//
//   h2 = u1', h5 = v1'
//   a_i = (u_i'-u1')/127, c_i = (v1'-v_i')/127
//   2x2:  (u2'-u3') h6 + (u4'-u3') h7 = a3-a2-a4
//         (v3'-v2') h6 + (v3'-v4') h7 = c3-c2-c4
//   h0 = u2' h6 + a2, h1 = u4' h7 + a4, h3 = v2' h6 - c2, h4 = v4' h7 - c4
//
// R2: ITEMS=2/thread, BLOCK=256 for MLP=4 on loads; streaming cache hints.

#define BLOCK 256
#define ITEMS 2

__device__ __forceinline__ void dlt_solve(const float4 o0, const float4 o1,
                                          float* __restrict__ row)
{
    const float up1 =   0.0f + 32.0f * o0.x;
    const float vp1 =   0.0f + 32.0f * o0.y;
    const float up2 = 127.0f + 32.0f * o0.z;
    const float vp2 =   0.0f + 32.0f * o0.w;
    const float up3 = 127.0f + 32.0f * o1.x;
    const float vp3 = 127.0f + 32.0f * o1.y;
    const float up4 =   0.0f + 32.0f * o1.z;
    const float vp4 = 127.0f + 32.0f * o1.w;

    const float inv127 = 1.0f / 127.0f;
    const float a2 = (up2 - up1) * inv127;
    const float a3 = (up3 - up1) * inv127;
    const float a4 = (up4 - up1) * inv127;
    const float c2 = (vp1 - vp2) * inv127;
    const float c3 = (vp1 - vp3) * inv127;
    const float c4 = (vp1 - vp4) * inv127;

    const float m00 = up2 - up3;
    const float m01 = up4 - up3;
    const float m10 = vp3 - vp2;
    const float m11 = vp3 - vp4;
    const float r0 = a3 - a2 - a4;
    const float r1 = c3 - c2 - c4;

    const float invdet = 1.0f / (m00 * m11 - m01 * m10);
    const float h6 = (r0 * m11 - m01 * r1) * invdet;
    const float h7 = (m00 * r1 - r0 * m10) * invdet;

    row[0] = up2 * h6 + a2;
    row[1] = up4 * h7 + a4;
    row[2] = up1;
    row[3] = vp2 * h6 - c2;
    row[4] = vp4 * h7 - c4;
    row[5] = vp1;
    row[6] = h6;
    row[7] = h7;
    row[8] = 1.0f;
}

__global__ void __launch_bounds__(BLOCK) tensor_dlt_kernel(
    const float* __restrict__ offset,  // [B, 8]
    float* __restrict__ out,           // [B, 9]
    int B)
{
    __shared__ float s[BLOCK * ITEMS * 9];

    const int base = blockIdx.x * (BLOCK * ITEMS);

    // Issue all loads up front: 2*ITEMS independent LDG.128 per thread.
    float4 o[ITEMS][2];
    #pragma unroll
    for (int it = 0; it < ITEMS; ++it) {
        const int b = base + it * BLOCK + threadIdx.x;
        if (b < B) {
            const float4* p = reinterpret_cast<const float4*>(offset) + (size_t)b * 2;
            o[it][0] = __ldcs(p + 0);
            o[it][1] = __ldcs(p + 1);
        }
    }

    #pragma unroll
    for (int it = 0; it < ITEMS; ++it) {
        const int b = base + it * BLOCK + threadIdx.x;
        if (b < B) {
            // stride-9 SMEM rows: gcd(9,32)=1 -> conflict-free
            dlt_solve(o[it][0], o[it][1], s + (it * BLOCK + threadIdx.x) * 9);
        }
    }
    __syncthreads();

    const int valid = min(BLOCK * ITEMS, B - base);
    float* dst = out + (size_t)base * 9;

    if (valid == BLOCK * ITEMS) {
        // BLOCK*ITEMS*9 = 4608 floats = 1152 float4, base 16B-aligned
        const float4* s4 = reinterpret_cast<const float4*>(s);
        float4* d4 = reinterpret_cast<float4*>(dst);
        #pragma unroll
        for (int i = threadIdx.x; i < (BLOCK * ITEMS * 9) / 4; i += BLOCK)
            __stcs(d4 + i, s4[i]);
    } else {
        const int n = valid * 9;
        for (int i = threadIdx.x; i < n; i += BLOCK)
            dst[i] = s[i];
    }
}

extern "C" void kernel_launch(void* const* d_in, const int* in_sizes, int n_in,
                              void* d_out, int out_size)
{
    const float* offset = (const float*)d_in[0];
    float* out = (float*)d_out;
    const int B = in_sizes[0] / 8;
    const int grid = (B + BLOCK * ITEMS - 1) / (BLOCK * ITEMS);
    tensor_dlt_kernel<<<grid, BLOCK>>>(offset, out, B);
}